// round 14
// baseline (speedup 1.0000x reference)
#include <cuda_runtime.h>
#include <cuda_bf16.h>
#include <math.h>

// Problem dims
#define TT 512
#define BB 64
#define II 512
#define HH 512

// Phase-2: 128 blocks = 16 groups (4 batches) x 8 j-tiles (64 j each).
#define NBLK 128
#define GRPS 16
#define GBLK 8
#define JT   64
#define BT   4
#define HSTR 520            // h_sh row stride in floats (512 + 8 pad)
#define RSTR 17             // reduction row stride in floats
#define NTHR 288            // 256 compute + 32 comm

__device__ __align__(16) float g_hbuf[2 * BB * HH];
__device__ __align__(16) unsigned g_arrive[NBLK];   // zero-init; monotonic

// ---- f32x2 helpers -------------------------------------------------------
__device__ __forceinline__ unsigned long long pack2(float x, float y) {
    unsigned long long r;
    asm("mov.b64 %0, {%1, %2};" : "=l"(r) : "f"(x), "f"(y));
    return r;
}
__device__ __forceinline__ float hadd2(unsigned long long v) {
    float lo, hi;
    asm("mov.b64 {%0, %1}, %2;" : "=f"(lo), "=f"(hi) : "l"(v));
    return lo + hi;
}
#define FMA2(c, a, b) \
    asm("fma.rn.f32x2 %0, %1, %2, %3;" : "=l"(c) : "l"(a), "l"(b), "l"(c))

#define BAR_COMPUTE() asm volatile("bar.sync 1, 256;" ::: "memory")

// ---------------------------------------------------------------------------
// Phase 1: xp = X @ W^T  (exact R5 kernel, ~430us measured)
// ---------------------------------------------------------------------------
__global__ void __launch_bounds__(256) gemm_xp_kernel(
    const float* __restrict__ X, const float* __restrict__ W,
    float* __restrict__ C)
{
    const int K = II, N = HH;
    __shared__ __align__(16) float As[16][128];
    __shared__ __align__(16) float Bs[16][128];

    const int bm = blockIdx.x * 128;
    const int bn = blockIdx.y * 128;
    const int tid = threadIdx.x;
    const int tx = tid & 15;
    const int ty = tid >> 4;

    float acc[8][8];
#pragma unroll
    for (int i = 0; i < 8; i++)
#pragma unroll
        for (int j = 0; j < 8; j++) acc[i][j] = 0.0f;

    for (int k0 = 0; k0 < K; k0 += 16) {
#pragma unroll
        for (int l = 0; l < 2; l++) {
            int idx = tid + l * 256;
            int r = idx >> 2;
            int c = (idx & 3) * 4;
            float4 va = *(const float4*)&X[(size_t)(bm + r) * K + k0 + c];
            As[c + 0][r] = va.x; As[c + 1][r] = va.y;
            As[c + 2][r] = va.z; As[c + 3][r] = va.w;
            float4 vb = *(const float4*)&W[(size_t)(bn + r) * K + k0 + c];
            Bs[c + 0][r] = vb.x; Bs[c + 1][r] = vb.y;
            Bs[c + 2][r] = vb.z; Bs[c + 3][r] = vb.w;
        }
        __syncthreads();

#pragma unroll
        for (int kk = 0; kk < 16; kk++) {
            float a[8], b[8];
            *(float4*)&a[0] = *(const float4*)&As[kk][ty * 8];
            *(float4*)&a[4] = *(const float4*)&As[kk][ty * 8 + 4];
            *(float4*)&b[0] = *(const float4*)&Bs[kk][tx * 8];
            *(float4*)&b[4] = *(const float4*)&Bs[kk][tx * 8 + 4];
#pragma unroll
            for (int i = 0; i < 8; i++)
#pragma unroll
                for (int j = 0; j < 8; j++)
                    acc[i][j] = fmaf(a[i], b[j], acc[i][j]);
        }
        __syncthreads();
    }

#pragma unroll
    for (int i = 0; i < 8; i++) {
        int row = bm + ty * 8 + i;
        float4 v0 = make_float4(acc[i][0], acc[i][1], acc[i][2], acc[i][3]);
        float4 v1 = make_float4(acc[i][4], acc[i][5], acc[i][6], acc[i][7]);
        *(float4*)&C[(size_t)row * N + bn + tx * 8]     = v0;
        *(float4*)&C[(size_t)row * N + bn + tx * 8 + 4] = v1;
    }
}

// ---------------------------------------------------------------------------
// Phase 2: persistent recurrence, warp-specialized chunked exchange.
//   288 threads: tid<256 compute (ks=tid>>4, jp=tid&15; W slab in regs),
//   warp 8 = comm: per step s, per chunk c (64 k from group block c):
//   poll g_arrive, pull 1KB chunk L2->h_sh[s&1], release via ready[s&1][c]=s.
//   Compute spins on ready (cheap LDS), FMAs chunk, accumulates in regs;
//   16-way split-k reduced via stride-17 smem; tanh; store + flag.
//   comp_done=s (set after FMAs certified by the reduction barrier) gives
//   the comm warp distance-2 buffer back-pressure.
// ---------------------------------------------------------------------------
__global__ void __launch_bounds__(NTHR) rnn_recurrence_kernel(
    const float* __restrict__ w_hh, float* __restrict__ out, int has_last)
{
    __shared__ __align__(16) float h_sh[2][BT][HSTR];   // 16.6KB
    __shared__ __align__(16) float red[256 * RSTR];     // 17.4KB
    __shared__ int ready[2][8];
    __shared__ int comp_done;
    __shared__ unsigned s_base;

    const int tid = threadIdx.x;
    const int bid = blockIdx.x;
    const int grp = bid >> 3;          // 0..15
    const int jt  = bid & 7;           // 0..7
    const int b0  = grp * BT;
    const int j0  = jt * JT;

    volatile int* v_ready = (volatile int*)&ready[0][0];
    volatile int* v_done  = (volatile int*)&comp_done;

    if (tid == 0) {
        s_base = *((volatile unsigned*)&g_arrive[bid]);
        *v_done = 0;
    }
    if (tid < 16) v_ready[tid] = 0;

    // ---- compute threads load W slab (absolute-chunk-indexed pairs)
    const int ks = tid >> 4;       // 0..15 (compute only)
    const int jp = tid & 15;
    const int cxor = ((ks >> 3) & 1) << 2;   // bit3 of k4=(c*16+ks) = ks bit3

    unsigned long long whh[4][16];
    if (tid < 256) {
#pragma unroll
        for (int jj = 0; jj < 4; jj++) {
            const float* wr = &w_hh[(size_t)(j0 + jp * 4 + jj) * HH + ks * 4];
#pragma unroll
            for (int c = 0; c < 8; c++) {
                float4 v = *(const float4*)&wr[c * 64];
                whh[jj][c * 2 + 0] = pack2(v.x, v.y);
                whh[jj][c * 2 + 1] = pack2(v.z, v.w);
            }
        }
    }
    __syncthreads();
    const unsigned base = s_base;

    // ======================= COMM WARP (tid 256..287) ======================
    if (tid >= 256) {
        const int ctid = tid - 256;
        const float4* hb4 = (const float4*)g_hbuf;
        for (int s = 1; s < TT; s++) {
            const int par  = s & 1;
            const int prev = (s - 1) & 1;
            // buffer reuse safety (distance 2)
            while (*v_done < s - 2) { __nanosleep(32); }
#pragma unroll 1
            for (int i = 0; i < 8; i++) {
                const int c = (jt + i) & 7;
                if (ctid == 0) {
                    const unsigned tgt = base + (unsigned)s;
                    const unsigned* fl = &g_arrive[grp * GBLK + c];
                    while (__ldcg(fl) < tgt) { __nanosleep(32); }
                }
                __syncwarp();
                __threadfence();   // order: flag observed before chunk loads
                // load chunk c: 4 b x 16 k4 = 64 f4
#pragma unroll
                for (int r = 0; r < 2; r++) {
                    int idx = ctid + r * 32;       // 0..63
                    int b  = idx >> 4;             // 0..3
                    int k4 = c * 16 + (idx & 15);
                    float4 v = __ldcg(&hb4[(size_t)prev * (BB * HH / 4)
                                           + (size_t)(b0 + b) * 128 + k4]);
                    int off = b * HSTR + ((k4 * 4) ^ (((k4 >> 3) & 1) << 2));
                    *(float4*)&h_sh[par][0][off] = v;
                }
                asm volatile("membar.cta;" ::: "memory");
                __syncwarp();
                if (ctid == 0) v_ready[par * 8 + c] = s;
            }
        }
        return;   // comm warp exits; no named-barrier participation
    }

    // ======================= COMPUTE THREADS (tid < 256) ===================
    const int gj = j0 + (tid & 63);
    const int gb = b0 + (tid >> 6);

    float* __restrict__ hall  = out;
    float* __restrict__ hlast = out + (size_t)TT * BB * HH;

    for (int s = 0; s < TT; s++) {
        float xp = hall[((size_t)s * BB + gb) * HH + gj];   // prefetch

        float hsum = 0.0f;
        if (s > 0) {
            const int par = s & 1;
            unsigned long long acc[4][4];
#pragma unroll
            for (int jj = 0; jj < 4; jj++)
#pragma unroll
                for (int bb = 0; bb < 4; bb++) acc[jj][bb] = 0ULL;

#pragma unroll 1
            for (int i = 0; i < 8; i++) {
                const int c = (jt + i) & 7;
                while (v_ready[par * 8 + c] < s) { /* spin (LDS bcast) */ }
                const int koff = (c * 64 + ks * 4) ^ cxor;
#pragma unroll
                for (int bb = 0; bb < 4; bb++) {
                    ulonglong2 hv =
                        *(const ulonglong2*)&h_sh[par][bb][koff];
#pragma unroll
                    for (int jj = 0; jj < 4; jj++) {
                        FMA2(acc[jj][bb], whh[jj][c * 2 + 0], hv.x);
                        FMA2(acc[jj][bb], whh[jj][c * 2 + 1], hv.y);
                    }
                }
            }

            // partials -> red[row][ks], row = bb*64 + jp*4 + jj
#pragma unroll
            for (int jj = 0; jj < 4; jj++)
#pragma unroll
                for (int bb = 0; bb < 4; bb++)
                    red[(bb * 64 + jp * 4 + jj) * RSTR + ks] =
                        hadd2(acc[jj][bb]);
            BAR_COMPUTE();          // also certifies all h_sh[par] reads done
            if (tid == 0) *v_done = s;

            const float* rr = &red[tid * RSTR];
            float s0 = 0.f, s1 = 0.f, s2 = 0.f, s3 = 0.f;
#pragma unroll
            for (int i = 0; i < 16; i += 4) {
                s0 += rr[i + 0];
                s1 += rr[i + 1];
                s2 += rr[i + 2];
                s3 += rr[i + 3];
            }
            hsum = (s0 + s1) + (s2 + s3);
        }

        float h = tanhf(xp + hsum);

        // state store first, then signal (hall store off critical path)
        g_hbuf[((size_t)(s & 1) * BB + gb) * HH + gj] = h;

        if (s != TT - 1) {
            BAR_COMPUTE();          // all g_hbuf stores issued; red free
            if (tid == 0) {
                __threadfence();
                *((volatile unsigned*)&g_arrive[bid]) = base + 1u + (unsigned)s;
            }
        }

        hall[((size_t)s * BB + gb) * HH + gj] = h;
        if (has_last && s == TT - 1)
            hlast[(size_t)gb * HH + gj] = h;
    }
}

// ---------------------------------------------------------------------------
extern "C" void kernel_launch(void* const* d_in, const int* in_sizes, int n_in,
                              void* d_out, int out_size) {
    const float* x    = (const float*)d_in[0];   // (T, B, I)
    const float* w_ih = (const float*)d_in[1];   // (H, I)
    const float* w_hh = (const float*)d_in[2];   // (H, H)
    float* out = (float*)d_out;

    dim3 g1((TT * BB) / 128, HH / 128);
    gemm_xp_kernel<<<g1, 256>>>(x, w_ih, out);

    int has_last = (out_size >= TT * BB * HH + BB * HH) ? 1 : 0;
    rnn_recurrence_kernel<<<NBLK, NTHR>>>(w_hh, out, has_last);
}

// round 16
// speedup vs baseline: 4.6741x; 4.6741x over previous
#include <cuda_runtime.h>
#include <cuda_bf16.h>
#include <math.h>

// Problem dims
#define TT 512
#define BB 64
#define II 512
#define HH 512

// Phase-2: 128 blocks = 8 groups (8 batches) x 16 j-tiles (32 j each).
#define NBLK 128
#define GRPS 8
#define GBLK 16
#define JT   32
#define BT   8
#define HSTR 520            // h_sh row stride in floats (512 + 8 pad)
#define RSTR 37             // reduction row stride in floats

__device__ __align__(16) float g_hbuf[2 * BB * HH];
__device__ __align__(16) unsigned g_arrive[NBLK];   // zero-init; monotonic

// ---- f32x2 helpers -------------------------------------------------------
__device__ __forceinline__ unsigned long long pack2(float x, float y) {
    unsigned long long r;
    asm("mov.b64 %0, {%1, %2};" : "=l"(r) : "f"(x), "f"(y));
    return r;
}
__device__ __forceinline__ float hadd2(unsigned long long v) {
    float lo, hi;
    asm("mov.b64 {%0, %1}, %2;" : "=f"(lo), "=f"(hi) : "l"(v));
    return lo + hi;
}
#define FMA2(c, a, b) \
    asm("fma.rn.f32x2 %0, %1, %2, %3;" : "=l"(c) : "l"(a), "l"(b), "l"(c))

__device__ __forceinline__ unsigned ld_acq_gpu(const unsigned* p) {
    unsigned v;
    asm volatile("ld.acquire.gpu.global.u32 %0, [%1];" : "=r"(v) : "l"(p));
    return v;
}
__device__ __forceinline__ void st_rel_gpu(unsigned* p, unsigned v) {
    asm volatile("st.release.gpu.global.u32 [%0], %1;" :: "l"(p), "r"(v)
                 : "memory");
}

// ---------------------------------------------------------------------------
// Phase 1: xp = X @ W^T  (exact R5 kernel, ~430us measured)
// ---------------------------------------------------------------------------
__global__ void __launch_bounds__(256) gemm_xp_kernel(
    const float* __restrict__ X, const float* __restrict__ W,
    float* __restrict__ C)
{
    const int K = II, N = HH;
    __shared__ __align__(16) float As[16][128];
    __shared__ __align__(16) float Bs[16][128];

    const int bm = blockIdx.x * 128;
    const int bn = blockIdx.y * 128;
    const int tid = threadIdx.x;
    const int tx = tid & 15;
    const int ty = tid >> 4;

    float acc[8][8];
#pragma unroll
    for (int i = 0; i < 8; i++)
#pragma unroll
        for (int j = 0; j < 8; j++) acc[i][j] = 0.0f;

    for (int k0 = 0; k0 < K; k0 += 16) {
#pragma unroll
        for (int l = 0; l < 2; l++) {
            int idx = tid + l * 256;
            int r = idx >> 2;
            int c = (idx & 3) * 4;
            float4 va = *(const float4*)&X[(size_t)(bm + r) * K + k0 + c];
            As[c + 0][r] = va.x; As[c + 1][r] = va.y;
            As[c + 2][r] = va.z; As[c + 3][r] = va.w;
            float4 vb = *(const float4*)&W[(size_t)(bn + r) * K + k0 + c];
            Bs[c + 0][r] = vb.x; Bs[c + 1][r] = vb.y;
            Bs[c + 2][r] = vb.z; Bs[c + 3][r] = vb.w;
        }
        __syncthreads();

#pragma unroll
        for (int kk = 0; kk < 16; kk++) {
            float a[8], b[8];
            *(float4*)&a[0] = *(const float4*)&As[kk][ty * 8];
            *(float4*)&a[4] = *(const float4*)&As[kk][ty * 8 + 4];
            *(float4*)&b[0] = *(const float4*)&Bs[kk][tx * 8];
            *(float4*)&b[4] = *(const float4*)&Bs[kk][tx * 8 + 4];
#pragma unroll
            for (int i = 0; i < 8; i++)
#pragma unroll
                for (int j = 0; j < 8; j++)
                    acc[i][j] = fmaf(a[i], b[j], acc[i][j]);
        }
        __syncthreads();
    }

#pragma unroll
    for (int i = 0; i < 8; i++) {
        int row = bm + ty * 8 + i;
        float4 v0 = make_float4(acc[i][0], acc[i][1], acc[i][2], acc[i][3]);
        float4 v1 = make_float4(acc[i][4], acc[i][5], acc[i][6], acc[i][7]);
        *(float4*)&C[(size_t)row * N + bn + tx * 8]     = v0;
        *(float4*)&C[(size_t)row * N + bn + tx * 8 + 4] = v1;
    }
}

// ---------------------------------------------------------------------------
// Phase 2: persistent recurrence — R5 engine (measured 1511us) with
// acquire/release flag path and MLP-batched h staging.
// ---------------------------------------------------------------------------
__global__ void __launch_bounds__(256) rnn_recurrence_kernel(
    const float* __restrict__ w_hh, float* __restrict__ out, int has_last)
{
    extern __shared__ __align__(16) float smem[];
    float* h_sh = smem;                       // [BT][HSTR] = 8 x 520
    float* red  = smem + BT * HSTR;           // [256][RSTR] = 256 x 37

    const int tid = threadIdx.x;
    const int bid = blockIdx.x;
    const int grp = bid >> 4;
    const int jt  = bid & 15;
    const int b0  = grp * BT;
    const int j0  = jt * JT;

    const int ks = tid >> 3;       // 0..31
    const int jp = tid & 7;        // 0..7
    const int kbase = ks * 16;
    const int cxor = (ks & 2) << 1;

    __shared__ unsigned s_base;
    if (tid == 0) s_base = *((volatile unsigned*)&g_arrive[bid]);

    // ---- W slab in registers (compile-time indices only!)
    unsigned long long wreg[4][8];
#pragma unroll
    for (int jj = 0; jj < 4; jj++) {
        const float* wr = &w_hh[(size_t)(j0 + jp * 4 + jj) * HH + kbase];
#pragma unroll
        for (int q = 0; q < 4; q++) {
            float4 v = *(const float4*)&wr[q * 4];
            wreg[jj][q * 2 + 0] = pack2(v.x, v.y);
            wreg[jj][q * 2 + 1] = pack2(v.z, v.w);
        }
    }
    __syncthreads();
    const unsigned base = s_base;

    const int gj = j0 + (tid & 31);
    const int gb = b0 + (tid >> 5);

    float* __restrict__ hall  = out;
    float* __restrict__ hlast = out + (size_t)TT * BB * HH;

    for (int t = 0; t < TT; t++) {
        float xp = hall[((size_t)t * BB + gb) * HH + gj];   // prefetch

        float hsum = 0.0f;
        if (t > 0) {
            // ---- group barrier: acquire-poll 16 peer flags
            if (tid < 32) {
                const unsigned tgt = base + (unsigned)t;
                const unsigned* fl = &g_arrive[grp * GBLK + (tid & 15)];
                for (;;) {
                    unsigned v = (tid < 16) ? ld_acq_gpu(fl) : tgt;
                    if (__all_sync(0xffffffffu, v >= tgt)) break;
                    __nanosleep(32);
                }
            }
            __syncthreads();

            // ---- stage h(t-1): batch 4 LDGs (MLP=4), then 4 STS.128
            {
                const int prev = (t - 1) & 1;
                const float4* src = (const float4*)&g_hbuf[
                    (size_t)prev * BB * HH + (size_t)b0 * HH];
                float4 v0 = __ldcg(&src[tid]);
                float4 v1 = __ldcg(&src[tid + 256]);
                float4 v2 = __ldcg(&src[tid + 512]);
                float4 v3 = __ldcg(&src[tid + 768]);
#pragma unroll
                for (int r = 0; r < 4; r++) {
                    int idx = tid + r * 256;
                    int b  = idx >> 7;
                    int k4 = idx & 127;
                    float4 v = (r == 0) ? v0 : (r == 1) ? v1
                             : (r == 2) ? v2 : v3;
                    int off = b * HSTR + ((k4 * 4) ^ (((k4 >> 3) & 1) << 2));
                    *(float4*)&h_sh[off] = v;
                }
            }
            __syncthreads();

            // ---- compute: acc[jj][bb] over 16 k (f32x2 pairs)
            unsigned long long acc[4][8];
#pragma unroll
            for (int jj = 0; jj < 4; jj++)
#pragma unroll
                for (int bb = 0; bb < 8; bb++) acc[jj][bb] = 0ULL;

#pragma unroll
            for (int q = 0; q < 4; q++) {
                const int koff = kbase + ((q * 4) ^ cxor);
#pragma unroll
                for (int bb = 0; bb < 8; bb++) {
                    ulonglong2 hv = *(const ulonglong2*)&h_sh[
                        bb * HSTR + koff];
#pragma unroll
                    for (int jj = 0; jj < 4; jj++) {
                        FMA2(acc[jj][bb], wreg[jj][q * 2 + 0], hv.x);
                        FMA2(acc[jj][bb], wreg[jj][q * 2 + 1], hv.y);
                    }
                }
            }

            // ---- partials -> red[row][ks], row = bb*32 + jp*4 + jj
#pragma unroll
            for (int jj = 0; jj < 4; jj++)
#pragma unroll
                for (int bb = 0; bb < 8; bb++)
                    red[(bb * 32 + jp * 4 + jj) * RSTR + ks] =
                        hadd2(acc[jj][bb]);
            __syncthreads();

            const float* rr = &red[tid * RSTR];
            float s = 0.0f;
#pragma unroll
            for (int i = 0; i < 32; i++) s += rr[i];
            hsum = s;
        }

        float h = tanhf(xp + hsum);

        // state store first, then signal (hall store off critical path)
        g_hbuf[((size_t)(t & 1) * BB + gb) * HH + gj] = h;

        if (t != TT - 1) {
            __syncthreads();               // fence.cta: all hbuf stores ordered
            if (tid == 0)
                st_rel_gpu(&g_arrive[bid], base + 1u + (unsigned)t);
        }

        hall[((size_t)t * BB + gb) * HH + gj] = h;
        if (has_last && t == TT - 1)
            hlast[(size_t)gb * HH + gj] = h;
    }
}

// ---------------------------------------------------------------------------
extern "C" void kernel_launch(void* const* d_in, const int* in_sizes, int n_in,
                              void* d_out, int out_size) {
    const float* x    = (const float*)d_in[0];   // (T, B, I)
    const float* w_ih = (const float*)d_in[1];   // (H, I)
    const float* w_hh = (const float*)d_in[2];   // (H, H)
    float* out = (float*)d_out;

    dim3 g1((TT * BB) / 128, HH / 128);
    gemm_xp_kernel<<<g1, 256>>>(x, w_ih, out);

    int smem_bytes = (BT * HSTR + 256 * RSTR) * (int)sizeof(float); // ~54KB
    cudaFuncSetAttribute(rnn_recurrence_kernel,
                         cudaFuncAttributeMaxDynamicSharedMemorySize, smem_bytes);
    int has_last = (out_size >= TT * BB * HH + BB * HH) ? 1 : 0;
    rnn_recurrence_kernel<<<NBLK, 256, smem_bytes>>>(w_hh, out, has_last);
}